// round 15
// baseline (speedup 1.0000x reference)
#include <cuda_runtime.h>
#include <cuda_fp16.h>
#include <cstdint>
#include <math.h>

// ---------------------------------------------------------------------------
// Problem constants
// ---------------------------------------------------------------------------
#define NBATCH 128
#define LTOK   196
#define CDIM   768
#define KCODES 4096
#define MROWS  (NBATCH * LTOK)        // 25088
#define INV_DELTA_EFF 30.0f           // 15.0 / 0.5
#define NORM_EPS 1e-5f

// GEMM tiling (portable HMMA mma.sync path)
#define BM 128
#define BN 128
#define BK 32
#define NCHUNK (CDIM / BK)            // 24
#define GTHREADS 256                  // 8 warps: 4x2 grid, warp tile 32x64
#define NSTAGE 5

// smem rows: 32 halves data + 8 pad = 80 B per row (conflict-free ldmatrix)
#define ROWB 80
#define ABUF_BYTES (128 * ROWB)       // 10240 (A)
#define BBUF_BYTES (128 * ROWB)       // 10240 (B)
#define OFF_BHI ABUF_BYTES
#define STAGE_BYTES (ABUF_BYTES + BBUF_BYTES)           // 20480
#define SMEM_GEMM (NSTAGE * STAGE_BYTES)                // 102400 -> 2 CTAs/SM

// ---------------------------------------------------------------------------
// Scratch
// ---------------------------------------------------------------------------
__device__ __half g_Ahi[(size_t)MROWS * CDIM];
__device__ __half g_Bhi[(size_t)KCODES * CDIM];
__device__ float  g_rowsum[MROWS];

// ---------------------------------------------------------------------------
// PTX helpers
// ---------------------------------------------------------------------------
__device__ __forceinline__ uint32_t smem_u32(const void* p) {
    uint32_t a;
    asm("{ .reg .u64 t; cvta.to.shared.u64 t, %1; cvt.u32.u64 %0, t; }" : "=r"(a) : "l"(p));
    return a;
}
#define CP_ASYNC16(dst, src) \
    asm volatile("cp.async.cg.shared.global [%0], [%1], 16;\n" :: "r"(dst), "l"(src))
#define CP_COMMIT() asm volatile("cp.async.commit_group;\n" ::: "memory")
#define CP_WAIT3()  asm volatile("cp.async.wait_group 3;\n" ::: "memory")
#define CP_WAIT2()  asm volatile("cp.async.wait_group 2;\n" ::: "memory")
#define CP_WAIT1()  asm volatile("cp.async.wait_group 1;\n" ::: "memory")
#define CP_WAIT0()  asm volatile("cp.async.wait_group 0;\n" ::: "memory")

__device__ __forceinline__ void ldsm_x4(uint32_t* r, uint32_t addr) {
    asm volatile("ldmatrix.sync.aligned.m8n8.x4.shared.b16 {%0,%1,%2,%3}, [%4];"
                 : "=r"(r[0]), "=r"(r[1]), "=r"(r[2]), "=r"(r[3]) : "r"(addr));
}
__device__ __forceinline__ void mma16816(float* c, const uint32_t* a, uint32_t b0, uint32_t b1) {
    asm volatile("mma.sync.aligned.m16n8k16.row.col.f32.f16.f16.f32 "
                 "{%0,%1,%2,%3}, {%4,%5,%6,%7}, {%8,%9}, {%0,%1,%2,%3};"
                 : "+f"(c[0]), "+f"(c[1]), "+f"(c[2]), "+f"(c[3])
                 : "r"(a[0]), "r"(a[1]), "r"(a[2]), "r"(a[3]), "r"(b0), "r"(b1));
}

// ---------------------------------------------------------------------------
// Kernel 1: row inv-L2-norm; write fp16 of xn; zero rowsum.
// ---------------------------------------------------------------------------
__global__ void prep_x_kernel(const float* __restrict__ x) {
    int gw = (blockIdx.x * blockDim.x + threadIdx.x) >> 5;
    int lane = threadIdx.x & 31;
    if (gw >= MROWS) return;
    int n = gw / LTOK, l = gw % LTOK;
    const float4* r4 = (const float4*)(x + ((size_t)n * 197 + l + 1) * CDIM);

    float4 v[6];
    float s = 0.0f;
#pragma unroll
    for (int i = 0; i < 6; ++i) {
        v[i] = r4[lane + i * 32];
        s += v[i].x * v[i].x + v[i].y * v[i].y + v[i].z * v[i].z + v[i].w * v[i].w;
    }
#pragma unroll
    for (int o = 16; o > 0; o >>= 1) s += __shfl_xor_sync(0xffffffffu, s, o);
    float inv = 1.0f / fmaxf(sqrtf(s), NORM_EPS);

    uint2* ah = (uint2*)(g_Ahi + (size_t)gw * CDIM);
#pragma unroll
    for (int i = 0; i < 6; ++i) {
        __half h[4];
        h[0] = __float2half_rn(v[i].x * inv);
        h[1] = __float2half_rn(v[i].y * inv);
        h[2] = __float2half_rn(v[i].z * inv);
        h[3] = __float2half_rn(v[i].w * inv);
        ah[lane + i * 32] = *(uint2*)h;
    }
    if (lane == 0) g_rowsum[gw] = 0.0f;
}

// ---------------------------------------------------------------------------
// Kernel 2: embedding -> fp16.
// ---------------------------------------------------------------------------
__global__ void conv_emb_kernel(const float* __restrict__ emb) {
    size_t i = (size_t)blockIdx.x * blockDim.x + threadIdx.x;
    float4 e = ((const float4*)emb)[i];
    __half h[4];
    h[0] = __float2half_rn(e.x);
    h[1] = __float2half_rn(e.y);
    h[2] = __float2half_rn(e.z);
    h[3] = __float2half_rn(e.w);
    ((uint2*)g_Bhi)[i] = *(uint2*)h;
}

// No-op kernel: keeps ncu's fixed sampling slot on the GEMM.
__global__ void noop_kernel() {}

// ---------------------------------------------------------------------------
// Kernel 3: HMMA GEMM  d = ah·bh + fused exp epilogue.
// CTA 128x128, 256 threads (8 warps 4x2, warp tile 32x64), 5-stage pipeline,
// 2 CTAs/SM (launch_bounds(256,2) -> 128-reg cap). Inner loop batches all
// 6 ldsm per k-step before the 16 MMAs: crossbar ratio 0.375 ldsm/HMMA and
// LDS latency amortized over the MMA run.
// ---------------------------------------------------------------------------
__device__ __forceinline__ void load_stage(uint32_t stage_sb, int k0, int row0, int col0, int tid) {
    // A: 128 rows x 4 chunks = 512; 2 per thread
#pragma unroll
    for (int j = 0; j < 2; ++j) {
        int c = tid * 2 + j;
        int row = c >> 2, ch = c & 3;
        const __half* src = g_Ahi + (size_t)(row0 + row) * CDIM + k0 + ch * 8;
        CP_ASYNC16(stage_sb + row * ROWB + ch * 16, src);
    }
    // B: 128 rows x 4 chunks = 512; 2 per thread
#pragma unroll
    for (int j = 0; j < 2; ++j) {
        int c = tid * 2 + j;
        int row = c >> 2, ch = c & 3;
        const __half* src = g_Bhi + (size_t)(col0 + row) * CDIM + k0 + ch * 8;
        CP_ASYNC16(stage_sb + OFF_BHI + row * ROWB + ch * 16, src);
    }
    CP_COMMIT();
}

__global__ __launch_bounds__(GTHREADS, 2) void gemm_exp_kernel(float* __restrict__ codes) {
    extern __shared__ char smem[];
    const uint32_t sb = smem_u32(smem);
    const int tid  = threadIdx.x;
    const int lane = tid & 31;
    const int warp = tid >> 5;
    const int wm = warp >> 1;              // 0..3 (32-row stripes)
    const int wn = warp & 1;               // 0..1 (64-col stripes)
    const int row0 = blockIdx.y * BM;
    const int col0 = blockIdx.x * BN;

    const int lm = lane & 7;
    const int lg = lane >> 3;

    const int a_row = wm * 32 + lm + (lg & 1) * 8;      // + mf*16
    const int a_kk  = (lg >> 1) * 8;
    const int b_row = wn * 64 + lm + (lg >> 1) * 8;     // + nf2*16
    const int b_kk  = (lg & 1) * 8;

    float acc[2][8][4];
#pragma unroll
    for (int i = 0; i < 2; ++i)
#pragma unroll
        for (int j = 0; j < 8; ++j)
#pragma unroll
            for (int c = 0; c < 4; ++c) acc[i][j][c] = 0.0f;

    load_stage(sb + 0 * STAGE_BYTES, 0 * BK, row0, col0, tid);
    load_stage(sb + 1 * STAGE_BYTES, 1 * BK, row0, col0, tid);
    load_stage(sb + 2 * STAGE_BYTES, 2 * BK, row0, col0, tid);
    load_stage(sb + 3 * STAGE_BYTES, 3 * BK, row0, col0, tid);

    for (int i = 0; i < NCHUNK; ++i) {
        if (i < NCHUNK - 3)      { CP_WAIT3(); }
        else if (i == NCHUNK - 3){ CP_WAIT2(); }
        else if (i == NCHUNK - 2){ CP_WAIT1(); }
        else                     { CP_WAIT0(); }
        __syncthreads();

        // Prefetch stage i+4 into the slot consumed in iteration i-1 (safe:
        // the barrier above guarantees all warps finished reading it).
        if (i + 4 < NCHUNK)
            load_stage(sb + ((i + 4) % NSTAGE) * STAGE_BYTES, (i + 4) * BK, row0, col0, tid);

        const uint32_t sA = sb + (i % NSTAGE) * STAGE_BYTES;
        const uint32_t sB = sA + OFF_BHI;

#pragma unroll
        for (int ks = 0; ks < 2; ++ks) {
            // Batch ALL fragment loads for this k-step first (6 ldsm),
            // then run the 16 MMAs — hides LDS latency behind tensor issue.
            uint32_t aH[2][4], bH[4][4];
#pragma unroll
            for (int mf = 0; mf < 2; ++mf) {
                uint32_t aoff = (uint32_t)((a_row + mf * 16) * ROWB + (ks * 16 + a_kk) * 2);
                ldsm_x4(aH[mf], sA + aoff);
            }
#pragma unroll
            for (int nf2 = 0; nf2 < 4; ++nf2) {
                uint32_t boff = (uint32_t)((b_row + nf2 * 16) * ROWB + (ks * 16 + b_kk) * 2);
                ldsm_x4(bH[nf2], sB + boff);
            }
#pragma unroll
            for (int nf2 = 0; nf2 < 4; ++nf2) {
#pragma unroll
                for (int mf = 0; mf < 2; ++mf) {
                    mma16816(acc[mf][nf2 * 2 + 0], aH[mf], bH[nf2][0], bH[nf2][1]);
                    mma16816(acc[mf][nf2 * 2 + 1], aH[mf], bH[nf2][2], bH[nf2][3]);
                }
            }
        }
    }

    // Epilogue: p = exp(30*d - 30); coalesced v2 stores; rowsum atomics.
#pragma unroll
    for (int mf = 0; mf < 2; ++mf) {
        int gr = row0 + wm * 32 + mf * 16 + (lane >> 2);   // rows gr and gr+8
        float s0 = 0.0f, s1 = 0.0f;
#pragma unroll
        for (int nf = 0; nf < 8; ++nf) {
            float* c = acc[mf][nf];
            float2 p0, p1;
            p0.x = __expf(fmaf(INV_DELTA_EFF, c[0], -INV_DELTA_EFF));
            p0.y = __expf(fmaf(INV_DELTA_EFF, c[1], -INV_DELTA_EFF));
            p1.x = __expf(fmaf(INV_DELTA_EFF, c[2], -INV_DELTA_EFF));
            p1.y = __expf(fmaf(INV_DELTA_EFF, c[3], -INV_DELTA_EFF));
            int gc = col0 + wn * 64 + nf * 8 + (lane & 3) * 2;
            *(float2*)(codes + (size_t)gr * KCODES + gc)       = p0;
            *(float2*)(codes + (size_t)(gr + 8) * KCODES + gc) = p1;
            s0 += p0.x + p0.y;
            s1 += p1.x + p1.y;
        }
        s0 += __shfl_xor_sync(0xffffffffu, s0, 1);
        s0 += __shfl_xor_sync(0xffffffffu, s0, 2);
        s1 += __shfl_xor_sync(0xffffffffu, s1, 1);
        s1 += __shfl_xor_sync(0xffffffffu, s1, 2);
        if ((lane & 3) == 0) {
            atomicAdd(&g_rowsum[gr], s0);
            atomicAdd(&g_rowsum[gr + 8], s1);
        }
    }
}

// ---------------------------------------------------------------------------
// Kernel 4: softmax normalize. One block per row; 4 float4 per thread;
// reciprocal hoisted.
// ---------------------------------------------------------------------------
__global__ __launch_bounds__(256) void scale_kernel(float* __restrict__ codes) {
    int r = blockIdx.x;
    float inv = 1.0f / g_rowsum[r];
    float4* row = (float4*)(codes + (size_t)r * KCODES);
    int t = threadIdx.x;
#pragma unroll
    for (int j = 0; j < 4; ++j) {
        float4 v = row[t + j * 256];
        v.x *= inv; v.y *= inv; v.z *= inv; v.w *= inv;
        row[t + j * 256] = v;
    }
}

// ---------------------------------------------------------------------------
// Kernel 5a: bow partial means. grid (128, 16), 64 threads.
// ---------------------------------------------------------------------------
__global__ __launch_bounds__(64) void bow_partial_kernel(
    const float* __restrict__ codes, float* __restrict__ bow)
{
    int n = blockIdx.x, kc = blockIdx.y, t = threadIdx.x;
    int col = kc * 256 + t * 4;
    float4 acc = make_float4(0.f, 0.f, 0.f, 0.f);
#pragma unroll 1
    for (int rr = 2; rr < 12; ++rr) {
#pragma unroll
        for (int cc = 2; cc < 12; ++cc) {
            int l = rr * 14 + cc;
            float4 v = *(const float4*)(codes + ((size_t)n * LTOK + l) * KCODES + col);
            acc.x += v.x; acc.y += v.y; acc.z += v.z; acc.w += v.w;
        }
    }
    acc.x *= 0.01f; acc.y *= 0.01f; acc.z *= 0.01f; acc.w *= 0.01f;
    *(float4*)(bow + (size_t)n * KCODES + col) = acc;
}

// ---------------------------------------------------------------------------
// Kernel 5b: L1-normalize bow rows.
// ---------------------------------------------------------------------------
__global__ __launch_bounds__(256) void bow_norm_kernel(float* __restrict__ bow) {
    int n = blockIdx.x, t = threadIdx.x;
    float4* row = (float4*)(bow + (size_t)n * KCODES);
    float4 v[4];
    float s = 0.0f;
#pragma unroll
    for (int j = 0; j < 4; ++j) {
        v[j] = row[t + j * 256];
        s += fabsf(v[j].x) + fabsf(v[j].y) + fabsf(v[j].z) + fabsf(v[j].w);
    }
    __shared__ float sred[256];
    sred[t] = s;
    __syncthreads();
    for (int o = 128; o > 0; o >>= 1) {
        if (t < o) sred[t] += sred[t + o];
        __syncthreads();
    }
    float inv = 1.0f / fmaxf(sred[0], NORM_EPS);
#pragma unroll
    for (int j = 0; j < 4; ++j) {
        v[j].x *= inv; v[j].y *= inv; v[j].z *= inv; v[j].w *= inv;
        row[t + j * 256] = v[j];
    }
}

// ---------------------------------------------------------------------------
// Launch
// ---------------------------------------------------------------------------
extern "C" void kernel_launch(void* const* d_in, const int* in_sizes, int n_in,
                              void* d_out, int out_size) {
    const float* x   = (const float*)d_in[0];
    const float* emb = (const float*)d_in[1];
    float* out_bow   = (float*)d_out;
    float* out_codes = (float*)d_out + (size_t)NBATCH * KCODES;

    cudaFuncSetAttribute(gemm_exp_kernel, cudaFuncAttributeMaxDynamicSharedMemorySize,
                         SMEM_GEMM);

    prep_x_kernel<<<MROWS * 32 / 256, 256>>>(x);
    conv_emb_kernel<<<(KCODES * CDIM / 4) / 256, 256>>>(emb);

    noop_kernel<<<1, 32>>>();   // keep ncu fixed sampling slot on the GEMM

    gemm_exp_kernel<<<dim3(KCODES / BN, MROWS / BM), GTHREADS, SMEM_GEMM>>>(out_codes);

    scale_kernel<<<MROWS, 256>>>(out_codes);
    bow_partial_kernel<<<dim3(NBATCH, 16), 64>>>(out_codes, out_bow);
    bow_norm_kernel<<<NBATCH, 256>>>(out_bow);
}

// round 17
// speedup vs baseline: 1.0941x; 1.0941x over previous
#include <cuda_runtime.h>
#include <cuda_fp16.h>
#include <cstdint>
#include <math.h>

// ---------------------------------------------------------------------------
// Problem constants
// ---------------------------------------------------------------------------
#define NBATCH 128
#define LTOK   196
#define CDIM   768
#define KCODES 4096
#define MROWS  (NBATCH * LTOK)        // 25088
#define INV_DELTA_EFF 30.0f           // 15.0 / 0.5
#define NORM_EPS 1e-5f

// GEMM tiling (portable HMMA mma.sync path)
#define BM 128
#define BN 128
#define BK 64
#define NCHUNK (CDIM / BK)            // 12
#define GTHREADS 512                  // 16 warps: 4x4 grid, warp tile 32x32
#define NSTAGE 3

// smem rows: 64 halves data + 16B pad = 144 B per row.
// Row stride 36 words; 8 consecutive rows hit word-groups stepping 4 mod 32
// -> the 8 rows of an ldmatrix land in 8 distinct 4-word bank groups.
#define ROWB 144
#define ABUF_BYTES (128 * ROWB)       // 18432 (A)
#define BBUF_BYTES (128 * ROWB)       // 18432 (B)
#define OFF_BHI ABUF_BYTES
#define STAGE_BYTES (ABUF_BYTES + BBUF_BYTES)           // 36864
#define SMEM_GEMM (NSTAGE * STAGE_BYTES)                // 110592 -> 2 CTAs/SM

// ---------------------------------------------------------------------------
// Scratch
// ---------------------------------------------------------------------------
__device__ __half g_Ahi[(size_t)MROWS * CDIM];
__device__ __half g_Bhi[(size_t)KCODES * CDIM];
__device__ float  g_rowsum[MROWS];

// ---------------------------------------------------------------------------
// PTX helpers
// ---------------------------------------------------------------------------
__device__ __forceinline__ uint32_t smem_u32(const void* p) {
    uint32_t a;
    asm("{ .reg .u64 t; cvta.to.shared.u64 t, %1; cvt.u32.u64 %0, t; }" : "=r"(a) : "l"(p));
    return a;
}
#define CP_ASYNC16(dst, src) \
    asm volatile("cp.async.cg.shared.global [%0], [%1], 16;\n" :: "r"(dst), "l"(src))
#define CP_COMMIT() asm volatile("cp.async.commit_group;\n" ::: "memory")
#define CP_WAIT1()  asm volatile("cp.async.wait_group 1;\n" ::: "memory")
#define CP_WAIT0()  asm volatile("cp.async.wait_group 0;\n" ::: "memory")

__device__ __forceinline__ void ldsm_x4(uint32_t* r, uint32_t addr) {
    asm volatile("ldmatrix.sync.aligned.m8n8.x4.shared.b16 {%0,%1,%2,%3}, [%4];"
                 : "=r"(r[0]), "=r"(r[1]), "=r"(r[2]), "=r"(r[3]) : "r"(addr));
}
__device__ __forceinline__ void mma16816(float* c, const uint32_t* a, uint32_t b0, uint32_t b1) {
    asm volatile("mma.sync.aligned.m16n8k16.row.col.f32.f16.f16.f32 "
                 "{%0,%1,%2,%3}, {%4,%5,%6,%7}, {%8,%9}, {%0,%1,%2,%3};"
                 : "+f"(c[0]), "+f"(c[1]), "+f"(c[2]), "+f"(c[3])
                 : "r"(a[0]), "r"(a[1]), "r"(a[2]), "r"(a[3]), "r"(b0), "r"(b1));
}

// ---------------------------------------------------------------------------
// Kernel 1: row inv-L2-norm; write fp16 of xn; zero rowsum.
// ---------------------------------------------------------------------------
__global__ void prep_x_kernel(const float* __restrict__ x) {
    int gw = (blockIdx.x * blockDim.x + threadIdx.x) >> 5;
    int lane = threadIdx.x & 31;
    if (gw >= MROWS) return;
    int n = gw / LTOK, l = gw % LTOK;
    const float4* r4 = (const float4*)(x + ((size_t)n * 197 + l + 1) * CDIM);

    float4 v[6];
    float s = 0.0f;
#pragma unroll
    for (int i = 0; i < 6; ++i) {
        v[i] = r4[lane + i * 32];
        s += v[i].x * v[i].x + v[i].y * v[i].y + v[i].z * v[i].z + v[i].w * v[i].w;
    }
#pragma unroll
    for (int o = 16; o > 0; o >>= 1) s += __shfl_xor_sync(0xffffffffu, s, o);
    float inv = 1.0f / fmaxf(sqrtf(s), NORM_EPS);

    uint2* ah = (uint2*)(g_Ahi + (size_t)gw * CDIM);
#pragma unroll
    for (int i = 0; i < 6; ++i) {
        __half h[4];
        h[0] = __float2half_rn(v[i].x * inv);
        h[1] = __float2half_rn(v[i].y * inv);
        h[2] = __float2half_rn(v[i].z * inv);
        h[3] = __float2half_rn(v[i].w * inv);
        ah[lane + i * 32] = *(uint2*)h;
    }
    if (lane == 0) g_rowsum[gw] = 0.0f;
}

// ---------------------------------------------------------------------------
// Kernel 2: embedding -> fp16.
// ---------------------------------------------------------------------------
__global__ void conv_emb_kernel(const float* __restrict__ emb) {
    size_t i = (size_t)blockIdx.x * blockDim.x + threadIdx.x;
    float4 e = ((const float4*)emb)[i];
    __half h[4];
    h[0] = __float2half_rn(e.x);
    h[1] = __float2half_rn(e.y);
    h[2] = __float2half_rn(e.z);
    h[3] = __float2half_rn(e.w);
    ((uint2*)g_Bhi)[i] = *(uint2*)h;
}

// No-op kernel: keeps ncu's fixed sampling slot on the GEMM.
__global__ void noop_kernel() {}

// ---------------------------------------------------------------------------
// Kernel 3: HMMA GEMM  d = ah·bh + fused exp epilogue.
// CTA 128x128, 512 threads (16 warps, warp tile 32x32), BK=64 chunks
// (12 barriers instead of 24), 3-stage pipeline, 2 CTAs/SM co-resident
// (launch_bounds(512,2) -> 64-reg cap) = 32 warps/SM.
// ---------------------------------------------------------------------------
__device__ __forceinline__ void load_stage(uint32_t stage_sb, int k0, int row0, int col0, int tid) {
    // A: 128 rows x 8 chunks of 16B = 1024 chunks; 2 per thread (512 threads)
#pragma unroll
    for (int j = 0; j < 2; ++j) {
        int c = tid * 2 + j;
        int row = c >> 3, ch = c & 7;
        const __half* src = g_Ahi + (size_t)(row0 + row) * CDIM + k0 + ch * 8;
        CP_ASYNC16(stage_sb + row * ROWB + ch * 16, src);
    }
    // B: 128 rows x 8 chunks = 1024 chunks; 2 per thread
#pragma unroll
    for (int j = 0; j < 2; ++j) {
        int c = tid * 2 + j;
        int row = c >> 3, ch = c & 7;
        const __half* src = g_Bhi + (size_t)(col0 + row) * CDIM + k0 + ch * 8;
        CP_ASYNC16(stage_sb + OFF_BHI + row * ROWB + ch * 16, src);
    }
    CP_COMMIT();
}

__global__ __launch_bounds__(GTHREADS, 2) void gemm_exp_kernel(float* __restrict__ codes) {
    extern __shared__ char smem[];
    const uint32_t sb = smem_u32(smem);
    const int tid  = threadIdx.x;
    const int lane = tid & 31;
    const int warp = tid >> 5;
    const int wm = warp >> 2;              // 0..3 (32-row stripes)
    const int wn = warp & 3;               // 0..3 (32-col stripes)
    const int row0 = blockIdx.y * BM;
    const int col0 = blockIdx.x * BN;

    const int lm = lane & 7;
    const int lg = lane >> 3;

    const int a_row = wm * 32 + lm + (lg & 1) * 8;      // + mf*16
    const int a_kk  = (lg >> 1) * 8;
    const int b_row = wn * 32 + lm + (lg >> 1) * 8;     // + nf2*16
    const int b_kk  = (lg & 1) * 8;

    float acc[2][4][4];
#pragma unroll
    for (int i = 0; i < 2; ++i)
#pragma unroll
        for (int j = 0; j < 4; ++j)
#pragma unroll
            for (int c = 0; c < 4; ++c) acc[i][j][c] = 0.0f;

    load_stage(sb + 0 * STAGE_BYTES, 0 * BK, row0, col0, tid);
    load_stage(sb + 1 * STAGE_BYTES, 1 * BK, row0, col0, tid);

    for (int i = 0; i < NCHUNK; ++i) {
        if (i < NCHUNK - 1) { CP_WAIT1(); } else { CP_WAIT0(); }
        __syncthreads();

        // Prefetch stage i+2 into the slot consumed in iteration i-1 (safe:
        // the barrier above guarantees all warps finished reading it).
        if (i + 2 < NCHUNK)
            load_stage(sb + ((i + 2) % NSTAGE) * STAGE_BYTES, (i + 2) * BK, row0, col0, tid);

        const uint32_t sA = sb + (i % NSTAGE) * STAGE_BYTES;
        const uint32_t sB = sA + OFF_BHI;

#pragma unroll
        for (int ks = 0; ks < 4; ++ks) {
            uint32_t aH[2][4], bH[2][4];
#pragma unroll
            for (int mf = 0; mf < 2; ++mf) {
                uint32_t aoff = (uint32_t)((a_row + mf * 16) * ROWB + (ks * 16 + a_kk) * 2);
                ldsm_x4(aH[mf], sA + aoff);
            }
#pragma unroll
            for (int nf2 = 0; nf2 < 2; ++nf2) {
                uint32_t boff = (uint32_t)((b_row + nf2 * 16) * ROWB + (ks * 16 + b_kk) * 2);
                ldsm_x4(bH[nf2], sB + boff);
            }
#pragma unroll
            for (int nf2 = 0; nf2 < 2; ++nf2) {
#pragma unroll
                for (int mf = 0; mf < 2; ++mf) {
                    mma16816(acc[mf][nf2 * 2 + 0], aH[mf], bH[nf2][0], bH[nf2][1]);
                    mma16816(acc[mf][nf2 * 2 + 1], aH[mf], bH[nf2][2], bH[nf2][3]);
                }
            }
        }
    }

    // Epilogue: p = exp(30*d - 30); coalesced v2 stores; rowsum atomics.
#pragma unroll
    for (int mf = 0; mf < 2; ++mf) {
        int gr = row0 + wm * 32 + mf * 16 + (lane >> 2);   // rows gr and gr+8
        float s0 = 0.0f, s1 = 0.0f;
#pragma unroll
        for (int nf = 0; nf < 4; ++nf) {
            float* c = acc[mf][nf];
            float2 p0, p1;
            p0.x = __expf(fmaf(INV_DELTA_EFF, c[0], -INV_DELTA_EFF));
            p0.y = __expf(fmaf(INV_DELTA_EFF, c[1], -INV_DELTA_EFF));
            p1.x = __expf(fmaf(INV_DELTA_EFF, c[2], -INV_DELTA_EFF));
            p1.y = __expf(fmaf(INV_DELTA_EFF, c[3], -INV_DELTA_EFF));
            int gc = col0 + wn * 32 + nf * 8 + (lane & 3) * 2;
            *(float2*)(codes + (size_t)gr * KCODES + gc)       = p0;
            *(float2*)(codes + (size_t)(gr + 8) * KCODES + gc) = p1;
            s0 += p0.x + p0.y;
            s1 += p1.x + p1.y;
        }
        s0 += __shfl_xor_sync(0xffffffffu, s0, 1);
        s0 += __shfl_xor_sync(0xffffffffu, s0, 2);
        s1 += __shfl_xor_sync(0xffffffffu, s1, 1);
        s1 += __shfl_xor_sync(0xffffffffu, s1, 2);
        if ((lane & 3) == 0) {
            atomicAdd(&g_rowsum[gr], s0);
            atomicAdd(&g_rowsum[gr + 8], s1);
        }
    }
}

// ---------------------------------------------------------------------------
// Kernel 4: softmax normalize. One block per row; 4 float4 per thread;
// reciprocal hoisted.
// ---------------------------------------------------------------------------
__global__ __launch_bounds__(256) void scale_kernel(float* __restrict__ codes) {
    int r = blockIdx.x;
    float inv = 1.0f / g_rowsum[r];
    float4* row = (float4*)(codes + (size_t)r * KCODES);
    int t = threadIdx.x;
#pragma unroll
    for (int j = 0; j < 4; ++j) {
        float4 v = row[t + j * 256];
        v.x *= inv; v.y *= inv; v.z *= inv; v.w *= inv;
        row[t + j * 256] = v;
    }
}

// ---------------------------------------------------------------------------
// Kernel 5a: bow partial means. grid (128, 16), 64 threads.
// ---------------------------------------------------------------------------
__global__ __launch_bounds__(64) void bow_partial_kernel(
    const float* __restrict__ codes, float* __restrict__ bow)
{
    int n = blockIdx.x, kc = blockIdx.y, t = threadIdx.x;
    int col = kc * 256 + t * 4;
    float4 acc = make_float4(0.f, 0.f, 0.f, 0.f);
#pragma unroll 1
    for (int rr = 2; rr < 12; ++rr) {
#pragma unroll
        for (int cc = 2; cc < 12; ++cc) {
            int l = rr * 14 + cc;
            float4 v = *(const float4*)(codes + ((size_t)n * LTOK + l) * KCODES + col);
            acc.x += v.x; acc.y += v.y; acc.z += v.z; acc.w += v.w;
        }
    }
    acc.x *= 0.01f; acc.y *= 0.01f; acc.z *= 0.01f; acc.w *= 0.01f;
    *(float4*)(bow + (size_t)n * KCODES + col) = acc;
}

// ---------------------------------------------------------------------------
// Kernel 5b: L1-normalize bow rows.
// ---------------------------------------------------------------------------
__global__ __launch_bounds__(256) void bow_norm_kernel(float* __restrict__ bow) {
    int n = blockIdx.x, t = threadIdx.x;
    float4* row = (float4*)(bow + (size_t)n * KCODES);
    float4 v[4];
    float s = 0.0f;
#pragma unroll
    for (int j = 0; j < 4; ++j) {
        v[j] = row[t + j * 256];
        s += fabsf(v[j].x) + fabsf(v[j].y) + fabsf(v[j].z) + fabsf(v[j].w);
    }
    __shared__ float sred[256];
    sred[t] = s;
    __syncthreads();
    for (int o = 128; o > 0; o >>= 1) {
        if (t < o) sred[t] += sred[t + o];
        __syncthreads();
    }
    float inv = 1.0f / fmaxf(sred[0], NORM_EPS);
#pragma unroll
    for (int j = 0; j < 4; ++j) {
        v[j].x *= inv; v[j].y *= inv; v[j].z *= inv; v[j].w *= inv;
        row[t + j * 256] = v[j];
    }
}

// ---------------------------------------------------------------------------
// Launch
// ---------------------------------------------------------------------------
extern "C" void kernel_launch(void* const* d_in, const int* in_sizes, int n_in,
                              void* d_out, int out_size) {
    const float* x   = (const float*)d_in[0];
    const float* emb = (const float*)d_in[1];
    float* out_bow   = (float*)d_out;
    float* out_codes = (float*)d_out + (size_t)NBATCH * KCODES;

    cudaFuncSetAttribute(gemm_exp_kernel, cudaFuncAttributeMaxDynamicSharedMemorySize,
                         SMEM_GEMM);

    prep_x_kernel<<<MROWS * 32 / 256, 256>>>(x);
    conv_emb_kernel<<<(KCODES * CDIM / 4) / 256, 256>>>(emb);

    noop_kernel<<<1, 32>>>();   // keep ncu fixed sampling slot on the GEMM

    gemm_exp_kernel<<<dim3(KCODES / BN, MROWS / BM), GTHREADS, SMEM_GEMM>>>(out_codes);

    scale_kernel<<<MROWS, 256>>>(out_codes);
    bow_partial_kernel<<<dim3(NBATCH, 16), 64>>>(out_codes, out_bow);
    bow_norm_kernel<<<NBATCH, 256>>>(out_bow);
}